// round 1
// baseline (speedup 1.0000x reference)
#include <cuda_runtime.h>
#include <math.h>

// Problem constants
#define BB   512
#define NN   64
#define NFG_ 1024
#define NFR_ 256
#define MROWS (BB * NN)            // 32768
#define OUT_OFF ((size_t)MROWS * NFG_)  // 33554432 floats: start of relation_graph in d_out

// Scratch (alloc-free rule: __device__ globals)
__device__ float g_theta[(size_t)MROWS * NFR_];
__device__ float g_phi[(size_t)MROWS * NFR_];
__device__ float g_agg[(size_t)MROWS * NFG_];

// ---------------------------------------------------------------------------
// Generic tiled SGEMM: C[M,N] = A[M,K] * W[K,N] (+ bias) (+ relu)
// 128x128 tile, BK=8, 256 threads, 8x8 per-thread micro-tile.
// Requires M%128==0, N%128==0, K%8==0 (true for all our shapes).
// ---------------------------------------------------------------------------
template <bool RELU, bool BIAS>
__global__ __launch_bounds__(256, 2)
void sgemm_kernel(const float* __restrict__ A, const float* __restrict__ W,
                  const float* __restrict__ bias, float* __restrict__ C,
                  int M, int N, int K)
{
    __shared__ float As[8][128];
    __shared__ float Bs[8][128];

    const int tid  = threadIdx.x;
    const int row0 = blockIdx.y << 7;
    const int col0 = blockIdx.x << 7;

    // A tile loads: 128 rows x 8 cols = 256 float4
    const int a_row = tid >> 1;
    const int a_col = (tid & 1) << 2;
    // B tile loads: 8 rows x 128 cols = 256 float4
    const int b_row = tid >> 5;
    const int b_col = (tid & 31) << 2;

    const int tx = tid & 15;
    const int ty = tid >> 4;

    const float* Ag = A + (size_t)(row0 + a_row) * K + a_col;
    const float* Bg = W + (size_t)b_row * N + col0 + b_col;

    float acc[8][8];
#pragma unroll
    for (int i = 0; i < 8; i++)
#pragma unroll
        for (int j = 0; j < 8; j++) acc[i][j] = 0.0f;

    for (int k0 = 0; k0 < K; k0 += 8) {
        float4 av = *(const float4*)(Ag + k0);
        float4 bv = *(const float4*)(Bg + (size_t)k0 * N);

        As[a_col + 0][a_row] = av.x;
        As[a_col + 1][a_row] = av.y;
        As[a_col + 2][a_row] = av.z;
        As[a_col + 3][a_row] = av.w;
        *(float4*)&Bs[b_row][b_col] = bv;
        __syncthreads();

#pragma unroll
        for (int k = 0; k < 8; k++) {
            float ar[8], br[8];
            *(float4*)&ar[0] = *(const float4*)&As[k][ty << 3];
            *(float4*)&ar[4] = *(const float4*)&As[k][(ty << 3) + 4];
            *(float4*)&br[0] = *(const float4*)&Bs[k][tx << 3];
            *(float4*)&br[4] = *(const float4*)&Bs[k][(tx << 3) + 4];
#pragma unroll
            for (int i = 0; i < 8; i++)
#pragma unroll
                for (int j = 0; j < 8; j++)
                    acc[i][j] = fmaf(ar[i], br[j], acc[i][j]);
        }
        __syncthreads();
    }

    float bb[8];
    if (BIAS) {
#pragma unroll
        for (int j = 0; j < 8; j++) bb[j] = bias[col0 + (tx << 3) + j];
    }

#pragma unroll
    for (int i = 0; i < 8; i++) {
        float* Cp = C + (size_t)(row0 + (ty << 3) + i) * N + col0 + (tx << 3);
        float v[8];
#pragma unroll
        for (int j = 0; j < 8; j++) {
            float x = acc[i][j];
            if (BIAS) x += bb[j];
            if (RELU) x = fmaxf(x, 0.0f);
            v[j] = x;
        }
        *(float4*)(Cp)     = make_float4(v[0], v[1], v[2], v[3]);
        *(float4*)(Cp + 4) = make_float4(v[4], v[5], v[6], v[7]);
    }
}

// ---------------------------------------------------------------------------
// Per-batch attention: sim = theta @ phi^T / 16, position mask, softmax.
// One block per b. theta row-major in smem; phi row-major with pad stride 257
// (odd stride -> conflict-free column-indexed scalar access).
// ---------------------------------------------------------------------------
#define PHS 257
#define SIMS 65
#define ATTN_SMEM_FLOATS (64*256 + 64*PHS + 64*SIMS + 128)

__global__ __launch_bounds__(256)
void attn_kernel(const float* __restrict__ theta, const float* __restrict__ phi,
                 const float* __restrict__ boxes, float* __restrict__ Rout)
{
    extern __shared__ float sm[];
    float* th   = sm;                    // 64 x 256
    float* ph   = th + 64 * 256;         // 64 x 257 (padded)
    float* simb = ph + 64 * PHS;         // 64 x 65  (padded)
    float* cx   = simb + 64 * SIMS;      // 64
    float* cy   = cx + 64;               // 64

    const int b   = blockIdx.x;
    const int tid = threadIdx.x;

    const float* thg = theta + (size_t)b * 64 * 256;
    const float* phg = phi   + (size_t)b * 64 * 256;

    for (int i = tid; i < 64 * 256 / 4; i += 256) {
        ((float4*)th)[i] = ((const float4*)thg)[i];
        float4 w = ((const float4*)phg)[i];
        int m  = i >> 6;
        int r4 = (i & 63) << 2;
        ph[m * PHS + r4 + 0] = w.x;
        ph[m * PHS + r4 + 1] = w.y;
        ph[m * PHS + r4 + 2] = w.z;
        ph[m * PHS + r4 + 3] = w.w;
    }
    if (tid < 64) {
        const float* bx = boxes + (size_t)b * 256 + tid * 4;
        cx[tid] = (bx[0] + bx[2]) * 0.5f;
        cy[tid] = (bx[1] + bx[3]) * 0.5f;
    }
    __syncthreads();

    // 16x16 threads, 4x4 micro-tile of the 64x64 sim matrix
    const int tx = tid & 15, ty = tid >> 4;
    const int n0 = ty << 2, m0 = tx << 2;
    float acc[4][4];
#pragma unroll
    for (int i = 0; i < 4; i++)
#pragma unroll
        for (int j = 0; j < 4; j++) acc[i][j] = 0.0f;

#pragma unroll 4
    for (int r = 0; r < 256; r++) {
        float a0 = th[(n0 + 0) * 256 + r];
        float a1 = th[(n0 + 1) * 256 + r];
        float a2 = th[(n0 + 2) * 256 + r];
        float a3 = th[(n0 + 3) * 256 + r];
        float p0 = ph[(m0 + 0) * PHS + r];
        float p1 = ph[(m0 + 1) * PHS + r];
        float p2 = ph[(m0 + 2) * PHS + r];
        float p3 = ph[(m0 + 3) * PHS + r];
        acc[0][0] = fmaf(a0, p0, acc[0][0]); acc[0][1] = fmaf(a0, p1, acc[0][1]);
        acc[0][2] = fmaf(a0, p2, acc[0][2]); acc[0][3] = fmaf(a0, p3, acc[0][3]);
        acc[1][0] = fmaf(a1, p0, acc[1][0]); acc[1][1] = fmaf(a1, p1, acc[1][1]);
        acc[1][2] = fmaf(a1, p2, acc[1][2]); acc[1][3] = fmaf(a1, p3, acc[1][3]);
        acc[2][0] = fmaf(a2, p0, acc[2][0]); acc[2][1] = fmaf(a2, p1, acc[2][1]);
        acc[2][2] = fmaf(a2, p2, acc[2][2]); acc[2][3] = fmaf(a2, p3, acc[2][3]);
        acc[3][0] = fmaf(a3, p0, acc[3][0]); acc[3][1] = fmaf(a3, p1, acc[3][1]);
        acc[3][2] = fmaf(a3, p2, acc[3][2]); acc[3][3] = fmaf(a3, p3, acc[3][3]);
    }

    const float THR   = 31.4f;     // 0.2 * OW(157)
    const float scale = 0.0625f;   // 1 / sqrt(256)
#pragma unroll
    for (int i = 0; i < 4; i++) {
        const int n = n0 + i;
#pragma unroll
        for (int j = 0; j < 4; j++) {
            const int m = m0 + j;
            float dx = cx[n] - cx[m];
            float dy = cy[n] - cy[m];
            float d  = sqrtf(dx * dx + dy * dy);
            simb[n * SIMS + m] = (d > THR) ? -INFINITY : acc[i][j] * scale;
        }
    }
    __syncthreads();

    // softmax per row (64 rows, one thread each; diagonal never masked)
    if (tid < 64) {
        float mx = -INFINITY;
        for (int m = 0; m < 64; m++) mx = fmaxf(mx, simb[tid * SIMS + m]);
        float s = 0.0f;
        for (int m = 0; m < 64; m++) {
            float e = expf(simb[tid * SIMS + m] - mx);
            simb[tid * SIMS + m] = e;
            s += e;
        }
        float inv = 1.0f / s;
        float* Rg = Rout + (size_t)b * 4096 + tid * 64;
        for (int m = 0; m < 64; m++) Rg[m] = simb[tid * SIMS + m] * inv;
    }
}

// ---------------------------------------------------------------------------
// agg = R @ feats, per b. Grid (8 col-chunks, 512 b). Block computes 64x128.
// ---------------------------------------------------------------------------
__global__ __launch_bounds__(256)
void agg_kernel(const float* __restrict__ R, const float* __restrict__ feats,
                float* __restrict__ agg)
{
    __shared__ float Rs[64 * 64];
    __shared__ float Fs[64 * 128];

    const int b   = blockIdx.y;
    const int cc  = blockIdx.x;
    const int tid = threadIdx.x;

    const float* Rg = R + (size_t)b * 4096;
    for (int i = tid; i < 1024; i += 256)
        ((float4*)Rs)[i] = ((const float4*)Rg)[i];

    const float* Fg = feats + (size_t)b * 64 * 1024 + cc * 128;
    for (int i = tid; i < 2048; i += 256) {
        int r  = i >> 5;
        int c4 = (i & 31) << 2;
        *(float4*)&Fs[r * 128 + c4] = *(const float4*)(Fg + (size_t)r * 1024 + c4);
    }
    __syncthreads();

    const int tx = tid & 15, ty = tid >> 4;
    const int n0 = ty << 2, c0 = tx << 3;
    float acc[4][8];
#pragma unroll
    for (int i = 0; i < 4; i++)
#pragma unroll
        for (int j = 0; j < 8; j++) acc[i][j] = 0.0f;

#pragma unroll 4
    for (int m = 0; m < 64; m++) {
        float f[8];
        *(float4*)&f[0] = *(const float4*)&Fs[m * 128 + c0];
        *(float4*)&f[4] = *(const float4*)&Fs[m * 128 + c0 + 4];
#pragma unroll
        for (int i = 0; i < 4; i++) {
            float rv = Rs[(n0 + i) * 64 + m];
#pragma unroll
            for (int j = 0; j < 8; j++)
                acc[i][j] = fmaf(rv, f[j], acc[i][j]);
        }
    }

    float* Og = agg + (size_t)b * 64 * 1024 + cc * 128;
#pragma unroll
    for (int i = 0; i < 4; i++) {
        float* p = Og + (size_t)(n0 + i) * 1024 + c0;
        *(float4*)(p)     = make_float4(acc[i][0], acc[i][1], acc[i][2], acc[i][3]);
        *(float4*)(p + 4) = make_float4(acc[i][4], acc[i][5], acc[i][6], acc[i][7]);
    }
}

// ---------------------------------------------------------------------------
extern "C" void kernel_launch(void* const* d_in, const int* in_sizes, int n_in,
                              void* d_out, int out_size)
{
    const float* feats   = (const float*)d_in[0];
    const float* boxes   = (const float*)d_in[1];
    const float* W_theta = (const float*)d_in[2];
    const float* b_theta = (const float*)d_in[3];
    const float* W_phi   = (const float*)d_in[4];
    const float* b_phi   = (const float*)d_in[5];
    const float* W_gcn   = (const float*)d_in[6];

    float* out = (float*)d_out;          // [512,64,1024]
    float* R   = out + OUT_OFF;          // [512,64,64]

    float *theta, *phi, *agg;
    cudaGetSymbolAddress((void**)&theta, g_theta);
    cudaGetSymbolAddress((void**)&phi,   g_phi);
    cudaGetSymbolAddress((void**)&agg,   g_agg);

    // theta / phi projections: [32768,1024] x [1024,256]
    sgemm_kernel<false, true><<<dim3(2, 256), 256>>>(feats, W_theta, b_theta, theta,
                                                     MROWS, NFR_, NFG_);
    sgemm_kernel<false, true><<<dim3(2, 256), 256>>>(feats, W_phi, b_phi, phi,
                                                     MROWS, NFR_, NFG_);

    // attention + softmax -> relation_graph (second output region)
    const int attn_smem = ATTN_SMEM_FLOATS * (int)sizeof(float);
    cudaFuncSetAttribute(attn_kernel, cudaFuncAttributeMaxDynamicSharedMemorySize,
                         attn_smem);
    attn_kernel<<<BB, 256, attn_smem>>>(theta, phi, boxes, R);

    // agg = R @ feats
    agg_kernel<<<dim3(8, BB), 256>>>(R, feats, agg);

    // out = relu(agg @ W_gcn): [32768,1024] x [1024,1024]
    sgemm_kernel<true, false><<<dim3(8, 256), 256>>>(agg, W_gcn, nullptr, out,
                                                     MROWS, NFG_, NFG_);
}

// round 3
// speedup vs baseline: 2.5408x; 2.5408x over previous
#include <cuda_runtime.h>
#include <cuda_fp16.h>
#include <math.h>
#include <stdint.h>

// Problem constants
#define BB   512
#define NN   64
#define NFG_ 1024
#define NFR_ 256
#define MROWS (BB * NN)                 // 32768
#define OUT_OFF ((size_t)MROWS * NFG_)  // relation_graph offset in d_out

// Scratch (__device__ globals: alloc-free rule)
__device__ __half g_Ahi[(size_t)MROWS * NFG_];
__device__ __half g_Alo[(size_t)MROWS * NFG_];
__device__ __half g_WTt_hi[(size_t)NFR_ * NFG_];
__device__ __half g_WTt_lo[(size_t)NFR_ * NFG_];
__device__ __half g_WTp_hi[(size_t)NFR_ * NFG_];
__device__ __half g_WTp_lo[(size_t)NFR_ * NFG_];
__device__ __half g_WTg_hi[(size_t)NFG_ * NFG_];
__device__ __half g_WTg_lo[(size_t)NFG_ * NFG_];
__device__ float  g_theta[(size_t)MROWS * NFR_];
__device__ float  g_phi[(size_t)MROWS * NFR_];
__device__ float  g_G[(size_t)MROWS * NFG_];

// ---------------------------------------------------------------------------
// PTX helpers (sm_80-class only: valid on plain sm_103 target)
// ---------------------------------------------------------------------------
__device__ __forceinline__ uint32_t smem_u32(const void* p) {
    uint32_t a;
    asm("{ .reg .u64 t; cvta.to.shared.u64 t, %1; cvt.u32.u64 %0, t; }"
        : "=r"(a) : "l"(p));
    return a;
}
__device__ __forceinline__ void cpa16(uint32_t dst, const void* src) {
    asm volatile("cp.async.cg.shared.global [%0], [%1], 16;"
                 :: "r"(dst), "l"(src));
}
__device__ __forceinline__ void cpa_commit() {
    asm volatile("cp.async.commit_group;" ::: "memory");
}
template <int N>
__device__ __forceinline__ void cpa_wait() {
    asm volatile("cp.async.wait_group %0;" :: "n"(N) : "memory");
}
__device__ __forceinline__ void ldsm4(uint32_t& r0, uint32_t& r1,
                                      uint32_t& r2, uint32_t& r3, uint32_t addr) {
    asm volatile("ldmatrix.sync.aligned.m8n8.x4.shared.b16 {%0,%1,%2,%3}, [%4];"
                 : "=r"(r0), "=r"(r1), "=r"(r2), "=r"(r3) : "r"(addr));
}
__device__ __forceinline__ void mma16816(float* c, uint32_t a0, uint32_t a1,
                                         uint32_t a2, uint32_t a3,
                                         uint32_t b0, uint32_t b1) {
    asm volatile(
        "mma.sync.aligned.m16n8k16.row.col.f32.f16.f16.f32 "
        "{%0,%1,%2,%3}, {%4,%5,%6,%7}, {%8,%9}, {%0,%1,%2,%3};"
        : "+f"(c[0]), "+f"(c[1]), "+f"(c[2]), "+f"(c[3])
        : "r"(a0), "r"(a1), "r"(a2), "r"(a3), "r"(b0), "r"(b1));
}

// ---------------------------------------------------------------------------
// feats split: x -> hi=f16(x), lo=f16(x-hi)
// ---------------------------------------------------------------------------
__global__ void split_feats(const float* __restrict__ x, __half* __restrict__ hi,
                            __half* __restrict__ lo, int n4)
{
    int i = blockIdx.x * blockDim.x + threadIdx.x;
    if (i >= n4) return;
    float4 v = ((const float4*)x)[i];
    __half h0 = __float2half_rn(v.x), h1 = __float2half_rn(v.y);
    __half h2 = __float2half_rn(v.z), h3 = __float2half_rn(v.w);
    __half l0 = __float2half_rn(v.x - __half2float(h0));
    __half l1 = __float2half_rn(v.y - __half2float(h1));
    __half l2 = __float2half_rn(v.z - __half2float(h2));
    __half l3 = __float2half_rn(v.w - __half2float(h3));
    ((__half2*)hi)[2 * i]     = __halves2half2(h0, h1);
    ((__half2*)hi)[2 * i + 1] = __halves2half2(h2, h3);
    ((__half2*)lo)[2 * i]     = __halves2half2(l0, l1);
    ((__half2*)lo)[2 * i + 1] = __halves2half2(l2, l3);
}

// ---------------------------------------------------------------------------
// Weight transpose + split: W[K,N] fp32 -> WT_hi/lo[N,K] fp16
// ---------------------------------------------------------------------------
__global__ void split_wt(const float* __restrict__ W, __half* __restrict__ hi,
                         __half* __restrict__ lo, int K, int N)
{
    __shared__ float t[32][33];
    const int n0 = blockIdx.x << 5, k0 = blockIdx.y << 5;
#pragma unroll
    for (int i = threadIdx.y; i < 32; i += 8)
        t[i][threadIdx.x] = W[(size_t)(k0 + i) * N + n0 + threadIdx.x];
    __syncthreads();
#pragma unroll
    for (int i = threadIdx.y; i < 32; i += 8) {
        float v = t[threadIdx.x][i];
        __half h = __float2half_rn(v);
        hi[(size_t)(n0 + i) * K + k0 + threadIdx.x] = h;
        lo[(size_t)(n0 + i) * K + k0 + threadIdx.x] =
            __float2half_rn(v - __half2float(h));
    }
}

// ---------------------------------------------------------------------------
// fp16 mma.sync GEMM: C[M,N] = sum_seg A_s[M,K] * B_s[N,K]^T (+bias)
// 128x128 block tile, BK=32, 8 warps (4M x 2N), warp tile 32x64,
// cp.async 2-stage double buffer, ldmatrix fragments. Requires
// M%128==0, N%128==0, K%32==0.
// ---------------------------------------------------------------------------
#define GSTR 40          // smem row stride in halves (80B) -> conflict-free
#define STAGE_BYTES 10240
#define B_BASE 20480

template <bool BIAS>
__global__ __launch_bounds__(256, 2)
void gemm_h(const __half* __restrict__ A0, const __half* __restrict__ A1,
            const __half* __restrict__ A2, const __half* __restrict__ B0,
            const __half* __restrict__ B1, const __half* __restrict__ B2,
            const float* __restrict__ bias, float* __restrict__ C,
            int M, int N, int K, int nseg)
{
    __shared__ __align__(16) char sm[2 * STAGE_BYTES * 2];
    const uint32_t sb = smem_u32(sm);

    const int tid  = threadIdx.x;
    const int wid  = tid >> 5, lane = tid & 31;
    const int wm   = wid & 3,  wn   = wid >> 2;
    const int g    = lane >> 2, tig = lane & 3;
    const int row0 = blockIdx.y << 7;
    const int col0 = blockIdx.x << 7;

    // cp.async per-thread source/dest mapping
    const int ra    = tid >> 1;                 // row within tile (0..127)
    const int cbase = (tid & 1) << 4;           // half offset (0 or 16)
    const uint32_t dst_l = (uint32_t)ra * 80u + ((uint32_t)(tid & 1) << 5);

    // ldmatrix per-lane local offsets
    const int t8 = lane >> 3, r8 = lane & 7;
    uint32_t aoff[2];
#pragma unroll
    for (int mi = 0; mi < 2; mi++) {
        int arow = wm * 32 + mi * 16 + (t8 & 1) * 8 + r8;
        aoff[mi] = (uint32_t)(arow * GSTR + (t8 >> 1) * 8) * 2u;
    }
    uint32_t boff[4];
#pragma unroll
    for (int j = 0; j < 4; j++) {
        int nrow = wn * 64 + (2 * j + (t8 >> 1)) * 8 + r8;
        boff[j] = (uint32_t)(nrow * GSTR + (t8 & 1) * 8) * 2u;
    }

    const int nc = K >> 5;
    const int nt = nc * nseg;

    float acc[2][8][4];
#pragma unroll
    for (int mi = 0; mi < 2; mi++)
#pragma unroll
        for (int ni = 0; ni < 8; ni++)
#pragma unroll
            for (int q = 0; q < 4; q++) acc[mi][ni][q] = 0.0f;

    // issue one chunk's cp.asyncs
    auto issue = [&](int t, int stage) {
        int seg = (t >= 2 * nc) ? 2 : (t >= nc) ? 1 : 0;
        const __half* Ag = (seg == 0) ? A0 : (seg == 1) ? A1 : A2;
        const __half* Bg = (seg == 0) ? B0 : (seg == 1) ? B1 : B2;
        int koff = (t - seg * nc) << 5;
        const __half* asrc = Ag + (size_t)(row0 + ra) * K + koff + cbase;
        uint32_t adst = sb + (uint32_t)stage * STAGE_BYTES + dst_l;
        cpa16(adst, asrc);
        cpa16(adst + 16, asrc + 8);
        const __half* bsrc = Bg + (size_t)(col0 + ra) * K + koff + cbase;
        uint32_t bdst = sb + B_BASE + (uint32_t)stage * STAGE_BYTES + dst_l;
        cpa16(bdst, bsrc);
        cpa16(bdst + 16, bsrc + 8);
        cpa_commit();
    };

    issue(0, 0);

    for (int t = 0; t < nt; t++) {
        const int stage = t & 1;
        if (t + 1 < nt) {
            issue(t + 1, (t + 1) & 1);
            cpa_wait<1>();
        } else {
            cpa_wait<0>();
        }
        __syncthreads();

        const uint32_t sA = sb + (uint32_t)stage * STAGE_BYTES;
        const uint32_t sB = sb + B_BASE + (uint32_t)stage * STAGE_BYTES;

#pragma unroll
        for (int ks = 0; ks < 2; ks++) {
            uint32_t a[2][4];
#pragma unroll
            for (int mi = 0; mi < 2; mi++)
                ldsm4(a[mi][0], a[mi][1], a[mi][2], a[mi][3],
                      sA + aoff[mi] + ks * 32);
            uint32_t b[8][2];
#pragma unroll
            for (int j = 0; j < 4; j++) {
                uint32_t q0, q1, q2, q3;
                ldsm4(q0, q1, q2, q3, sB + boff[j] + ks * 32);
                b[2 * j][0] = q0;  b[2 * j][1] = q1;
                b[2 * j + 1][0] = q2;  b[2 * j + 1][1] = q3;
            }
#pragma unroll
            for (int mi = 0; mi < 2; mi++)
#pragma unroll
                for (int ni = 0; ni < 8; ni++)
                    mma16816(acc[mi][ni], a[mi][0], a[mi][1], a[mi][2], a[mi][3],
                             b[ni][0], b[ni][1]);
        }
        __syncthreads();
    }

    // Epilogue
#pragma unroll
    for (int mi = 0; mi < 2; mi++) {
#pragma unroll
        for (int ni = 0; ni < 8; ni++) {
            int r = row0 + wm * 32 + mi * 16 + g;
            int c = col0 + wn * 64 + ni * 8 + tig * 2;
            float b0 = 0.0f, b1 = 0.0f;
            if (BIAS) { b0 = bias[c]; b1 = bias[c + 1]; }
            float2 v0 = make_float2(acc[mi][ni][0] + b0, acc[mi][ni][1] + b1);
            float2 v1 = make_float2(acc[mi][ni][2] + b0, acc[mi][ni][3] + b1);
            *(float2*)(C + (size_t)r * N + c)       = v0;
            *(float2*)(C + (size_t)(r + 8) * N + c) = v1;
        }
    }
}

// ---------------------------------------------------------------------------
// Per-batch attention: sim = theta @ phi^T / 16, position mask, softmax -> R
// ---------------------------------------------------------------------------
#define PHS 257
#define SIMS 65
#define ATTN_SMEM_FLOATS (64 * 256 + 64 * PHS + 64 * SIMS + 128)

__global__ __launch_bounds__(256)
void attn_kernel(const float* __restrict__ theta, const float* __restrict__ phi,
                 const float* __restrict__ boxes, float* __restrict__ Rout)
{
    extern __shared__ float smf[];
    float* th   = smf;
    float* ph   = th + 64 * 256;
    float* simb = ph + 64 * PHS;
    float* cx   = simb + 64 * SIMS;
    float* cy   = cx + 64;

    const int b   = blockIdx.x;
    const int tid = threadIdx.x;

    const float* thg = theta + (size_t)b * 64 * 256;
    const float* phg = phi   + (size_t)b * 64 * 256;

    for (int i = tid; i < 64 * 256 / 4; i += 256) {
        ((float4*)th)[i] = ((const float4*)thg)[i];
        float4 w = ((const float4*)phg)[i];
        int m  = i >> 6;
        int r4 = (i & 63) << 2;
        ph[m * PHS + r4 + 0] = w.x;
        ph[m * PHS + r4 + 1] = w.y;
        ph[m * PHS + r4 + 2] = w.z;
        ph[m * PHS + r4 + 3] = w.w;
    }
    if (tid < 64) {
        const float* bx = boxes + (size_t)b * 256 + tid * 4;
        cx[tid] = (bx[0] + bx[2]) * 0.5f;
        cy[tid] = (bx[1] + bx[3]) * 0.5f;
    }
    __syncthreads();

    const int tx = tid & 15, ty = tid >> 4;
    const int n0 = ty << 2, m0 = tx << 2;
    float acc[4][4];
#pragma unroll
    for (int i = 0; i < 4; i++)
#pragma unroll
        for (int j = 0; j < 4; j++) acc[i][j] = 0.0f;

#pragma unroll 4
    for (int r = 0; r < 256; r++) {
        float a0 = th[(n0 + 0) * 256 + r];
        float a1 = th[(n0 + 1) * 256 + r];
        float a2 = th[(n0 + 2) * 256 + r];
        float a3 = th[(n0 + 3) * 256 + r];
        float p0 = ph[(m0 + 0) * PHS + r];
        float p1 = ph[(m0 + 1) * PHS + r];
        float p2 = ph[(m0 + 2) * PHS + r];
        float p3 = ph[(m0 + 3) * PHS + r];
        acc[0][0] = fmaf(a0, p0, acc[0][0]); acc[0][1] = fmaf(a0, p1, acc[0][1]);
        acc[0][2] = fmaf(a0, p2, acc[0][2]); acc[0][3] = fmaf(a0, p3, acc[0][3]);
        acc[1][0] = fmaf(a1, p0, acc[1][0]); acc[1][1] = fmaf(a1, p1, acc[1][1]);
        acc[1][2] = fmaf(a1, p2, acc[1][2]); acc[1][3] = fmaf(a1, p3, acc[1][3]);
        acc[2][0] = fmaf(a2, p0, acc[2][0]); acc[2][1] = fmaf(a2, p1, acc[2][1]);
        acc[2][2] = fmaf(a2, p2, acc[2][2]); acc[2][3] = fmaf(a2, p3, acc[2][3]);
        acc[3][0] = fmaf(a3, p0, acc[3][0]); acc[3][1] = fmaf(a3, p1, acc[3][1]);
        acc[3][2] = fmaf(a3, p2, acc[3][2]); acc[3][3] = fmaf(a3, p3, acc[3][3]);
    }

    const float THR   = 31.4f;   // 0.2 * OW
    const float scale = 0.0625f; // 1/sqrt(256)
#pragma unroll
    for (int i = 0; i < 4; i++) {
        const int n = n0 + i;
#pragma unroll
        for (int j = 0; j < 4; j++) {
            const int m = m0 + j;
            float dx = cx[n] - cx[m];
            float dy = cy[n] - cy[m];
            float d  = sqrtf(dx * dx + dy * dy);
            simb[n * SIMS + m] = (d > THR) ? -INFINITY : acc[i][j] * scale;
        }
    }
    __syncthreads();

    if (tid < 64) {
        float mx = -INFINITY;
        for (int m = 0; m < 64; m++) mx = fmaxf(mx, simb[tid * SIMS + m]);
        float s = 0.0f;
        for (int m = 0; m < 64; m++) {
            float e = expf(simb[tid * SIMS + m] - mx);
            simb[tid * SIMS + m] = e;
            s += e;
        }
        float inv = 1.0f / s;
        float* Rg = Rout + (size_t)b * 4096 + tid * 64;
        for (int m = 0; m < 64; m++) Rg[m] = simb[tid * SIMS + m] * inv;
    }
}

// ---------------------------------------------------------------------------
// out = relu(R @ G), per b. Grid (8 col-chunks, 512 b). Block: 64x128 tile.
// ---------------------------------------------------------------------------
__global__ __launch_bounds__(256)
void rg_kernel(const float* __restrict__ R, const float* __restrict__ G,
               float* __restrict__ out)
{
    __shared__ float Rs[64 * 64];
    __shared__ float Fs[64 * 128];

    const int b   = blockIdx.y;
    const int cc  = blockIdx.x;
    const int tid = threadIdx.x;

    const float* Rg = R + (size_t)b * 4096;
    for (int i = tid; i < 1024; i += 256)
        ((float4*)Rs)[i] = ((const float4*)Rg)[i];

    const float* Fg = G + (size_t)b * 64 * 1024 + cc * 128;
    for (int i = tid; i < 2048; i += 256) {
        int r  = i >> 5;
        int c4 = (i & 31) << 2;
        *(float4*)&Fs[r * 128 + c4] = *(const float4*)(Fg + (size_t)r * 1024 + c4);
    }
    __syncthreads();

    const int tx = tid & 15, ty = tid >> 4;
    const int n0 = ty << 2, c0 = tx << 3;
    float acc[4][8];
#pragma unroll
    for (int i = 0; i < 4; i++)
#pragma unroll
        for (int j = 0; j < 8; j++) acc[i][j] = 0.0f;

#pragma unroll 4
    for (int m = 0; m < 64; m++) {
        float f[8];
        *(float4*)&f[0] = *(const float4*)&Fs[m * 128 + c0];
        *(float4*)&f[4] = *(const float4*)&Fs[m * 128 + c0 + 4];
#pragma unroll
        for (int i = 0; i < 4; i++) {
            float rv = Rs[(n0 + i) * 64 + m];
#pragma unroll
            for (int j = 0; j < 8; j++)
                acc[i][j] = fmaf(rv, f[j], acc[i][j]);
        }
    }

    float* Og = out + (size_t)b * 64 * 1024 + cc * 128;
#pragma unroll
    for (int i = 0; i < 4; i++) {
        float* p = Og + (size_t)(n0 + i) * 1024 + c0;
        float v[8];
#pragma unroll
        for (int j = 0; j < 8; j++) v[j] = fmaxf(acc[i][j], 0.0f);
        *(float4*)(p)     = make_float4(v[0], v[1], v[2], v[3]);
        *(float4*)(p + 4) = make_float4(v[4], v[5], v[6], v[7]);
    }
}

// ---------------------------------------------------------------------------
extern "C" void kernel_launch(void* const* d_in, const int* in_sizes, int n_in,
                              void* d_out, int out_size)
{
    const float* feats   = (const float*)d_in[0];
    const float* boxes   = (const float*)d_in[1];
    const float* W_theta = (const float*)d_in[2];
    const float* b_theta = (const float*)d_in[3];
    const float* W_phi   = (const float*)d_in[4];
    const float* b_phi   = (const float*)d_in[5];
    const float* W_gcn   = (const float*)d_in[6];

    float* out = (float*)d_out;
    float* R   = out + OUT_OFF;

    __half *Ahi, *Alo, *wtt_h, *wtt_l, *wtp_h, *wtp_l, *wtg_h, *wtg_l;
    float *theta, *phi, *G;
    cudaGetSymbolAddress((void**)&Ahi,   g_Ahi);
    cudaGetSymbolAddress((void**)&Alo,   g_Alo);
    cudaGetSymbolAddress((void**)&wtt_h, g_WTt_hi);
    cudaGetSymbolAddress((void**)&wtt_l, g_WTt_lo);
    cudaGetSymbolAddress((void**)&wtp_h, g_WTp_hi);
    cudaGetSymbolAddress((void**)&wtp_l, g_WTp_lo);
    cudaGetSymbolAddress((void**)&wtg_h, g_WTg_hi);
    cudaGetSymbolAddress((void**)&wtg_l, g_WTg_lo);
    cudaGetSymbolAddress((void**)&theta, g_theta);
    cudaGetSymbolAddress((void**)&phi,   g_phi);
    cudaGetSymbolAddress((void**)&G,     g_G);

    // 1) split/convert operands to fp16 (hi/lo)
    const int n4 = MROWS * NFG_ / 4;
    split_feats<<<n4 / 256, 256>>>(feats, Ahi, Alo, n4);
    split_wt<<<dim3(NFR_ / 32, NFG_ / 32), dim3(32, 8)>>>(W_theta, wtt_h, wtt_l,
                                                          NFG_, NFR_);
    split_wt<<<dim3(NFR_ / 32, NFG_ / 32), dim3(32, 8)>>>(W_phi, wtp_h, wtp_l,
                                                          NFG_, NFR_);
    split_wt<<<dim3(NFG_ / 32, NFG_ / 32), dim3(32, 8)>>>(W_gcn, wtg_h, wtg_l,
                                                          NFG_, NFG_);

    // 2) theta/phi projections, 3-segment split-fp16 (hi*hi + hi*lo + lo*hi)
    gemm_h<true><<<dim3(NFR_ / 128, MROWS / 128), 256>>>(
        Ahi, Ahi, Alo, wtt_h, wtt_l, wtt_h, b_theta, theta,
        MROWS, NFR_, NFG_, 3);
    gemm_h<true><<<dim3(NFR_ / 128, MROWS / 128), 256>>>(
        Ahi, Ahi, Alo, wtp_h, wtp_l, wtp_h, b_phi, phi,
        MROWS, NFR_, NFG_, 3);

    // 3) G = feats @ W_gcn (single fp16 term)
    gemm_h<false><<<dim3(NFG_ / 128, MROWS / 128), 256>>>(
        Ahi, Ahi, Alo, wtg_h, wtg_h, wtg_h, nullptr, G,
        MROWS, NFG_, NFG_, 1);

    // 4) attention + softmax -> relation_graph
    const int attn_smem = ATTN_SMEM_FLOATS * (int)sizeof(float);
    cudaFuncSetAttribute(attn_kernel, cudaFuncAttributeMaxDynamicSharedMemorySize,
                         attn_smem);
    attn_kernel<<<BB, 256, attn_smem>>>(theta, phi, boxes, R);

    // 5) out = relu(R @ G)  (== relu((R @ feats) @ W_gcn) by associativity)
    rg_kernel<<<dim3(8, BB), 256>>>(R, G, out);
}

// round 8
// speedup vs baseline: 3.5824x; 1.4099x over previous
#include <cuda_runtime.h>
#include <cuda_fp16.h>
#include <math.h>
#include <stdint.h>

// Problem constants
#define BB   512
#define NFG_ 1024
#define NFR_ 256
#define MROWS 32768
#define OUT_OFF ((size_t)MROWS * NFG_)

// Scratch (__device__ globals: alloc-free rule)
__device__ __half g_Ahi[(size_t)MROWS * NFG_];
__device__ __half g_Alo[(size_t)MROWS * NFG_];
__device__ __half g_Wc_hi[512 * NFG_];          // [W_theta^T ; W_phi^T]
__device__ __half g_Wc_lo[512 * NFG_];
__device__ __half g_Wg_hi[(size_t)NFG_ * NFG_];
__device__ __half g_Wg_lo[(size_t)NFG_ * NFG_];
__device__ __half g_TPh[(size_t)MROWS * 512];   // [theta|phi] fp16 hi
__device__ __half g_TPl[(size_t)MROWS * 512];
__device__ __half g_Gh[(size_t)MROWS * NFG_];   // G = feats@W_gcn hi
__device__ __half g_Gl[(size_t)MROWS * NFG_];
__device__ __half g_Rh[(size_t)MROWS * 64];
__device__ __half g_Rl[(size_t)MROWS * 64];

// ---------------------------------------------------------------------------
// PTX helpers (sm_80-class: valid on plain sm_103 target)
// ---------------------------------------------------------------------------
__device__ __forceinline__ uint32_t smem_u32(const void* p) {
    uint32_t a;
    asm("{ .reg .u64 t; cvta.to.shared.u64 t, %1; cvt.u32.u64 %0, t; }"
        : "=r"(a) : "l"(p));
    return a;
}
__device__ __forceinline__ void cpa16(uint32_t dst, const void* src) {
    asm volatile("cp.async.cg.shared.global [%0], [%1], 16;"
                 :: "r"(dst), "l"(src));
}
__device__ __forceinline__ void cpa_commit() {
    asm volatile("cp.async.commit_group;" ::: "memory");
}
template <int N>
__device__ __forceinline__ void cpa_wait() {
    asm volatile("cp.async.wait_group %0;" :: "n"(N) : "memory");
}
__device__ __forceinline__ void ldsm4(uint32_t* r, uint32_t addr) {
    asm volatile("ldmatrix.sync.aligned.m8n8.x4.shared.b16 {%0,%1,%2,%3}, [%4];"
                 : "=r"(r[0]), "=r"(r[1]), "=r"(r[2]), "=r"(r[3]) : "r"(addr));
}
__device__ __forceinline__ void ldsm4t(uint32_t* r, uint32_t addr) {
    asm volatile("ldmatrix.sync.aligned.m8n8.x4.trans.shared.b16 {%0,%1,%2,%3}, [%4];"
                 : "=r"(r[0]), "=r"(r[1]), "=r"(r[2]), "=r"(r[3]) : "r"(addr));
}
__device__ __forceinline__ void mma16816(float* c, const uint32_t* a,
                                         uint32_t b0, uint32_t b1) {
    asm volatile(
        "mma.sync.aligned.m16n8k16.row.col.f32.f16.f16.f32 "
        "{%0,%1,%2,%3}, {%4,%5,%6,%7}, {%8,%9}, {%0,%1,%2,%3};"
        : "+f"(c[0]), "+f"(c[1]), "+f"(c[2]), "+f"(c[3])
        : "r"(a[0]), "r"(a[1]), "r"(a[2]), "r"(a[3]), "r"(b0), "r"(b1));
}

// ---------------------------------------------------------------------------
// feats split: x -> hi=f16(x), lo=f16(x-hi)
// ---------------------------------------------------------------------------
__global__ void split_feats(const float* __restrict__ x, __half* __restrict__ hi,
                            __half* __restrict__ lo, int n4)
{
    int i = blockIdx.x * blockDim.x + threadIdx.x;
    if (i >= n4) return;
    float4 v = ((const float4*)x)[i];
    __half h0 = __float2half_rn(v.x), h1 = __float2half_rn(v.y);
    __half h2 = __float2half_rn(v.z), h3 = __float2half_rn(v.w);
    __half l0 = __float2half_rn(v.x - __half2float(h0));
    __half l1 = __float2half_rn(v.y - __half2float(h1));
    __half l2 = __float2half_rn(v.z - __half2float(h2));
    __half l3 = __float2half_rn(v.w - __half2float(h3));
    ((__half2*)hi)[2 * i]     = __halves2half2(h0, h1);
    ((__half2*)hi)[2 * i + 1] = __halves2half2(h2, h3);
    ((__half2*)lo)[2 * i]     = __halves2half2(l0, l1);
    ((__half2*)lo)[2 * i + 1] = __halves2half2(l2, l3);
}

// ---------------------------------------------------------------------------
// Weight transpose + split: W[K,N] fp32 -> WT_hi/lo[N,K] fp16
// ---------------------------------------------------------------------------
__global__ void split_wt(const float* __restrict__ W, __half* __restrict__ hi,
                         __half* __restrict__ lo, int K, int N)
{
    __shared__ float t[32][33];
    const int n0 = blockIdx.x << 5, k0 = blockIdx.y << 5;
#pragma unroll
    for (int i = threadIdx.y; i < 32; i += 8)
        t[i][threadIdx.x] = W[(size_t)(k0 + i) * N + n0 + threadIdx.x];
    __syncthreads();
#pragma unroll
    for (int i = threadIdx.y; i < 32; i += 8) {
        float v = t[threadIdx.x][i];
        __half h = __float2half_rn(v);
        hi[(size_t)(n0 + i) * K + k0 + threadIdx.x] = h;
        lo[(size_t)(n0 + i) * K + k0 + threadIdx.x] =
            __float2half_rn(v - __half2float(h));
    }
}

// ---------------------------------------------------------------------------
// fp16 mma.sync GEMM, single-pass multi-segment.
//   SPLIT: C = Ah*Bh + Ah*Bl + Al*Bh   else C = Ah*Bh
// Block 128x128, BK=32, 8 warps (4m x 2n), NSTAGE-deep cp.async pipeline.
// Output written as fp16 hi/lo pair. Bias: col<256 -> bias0, else bias1.
// ---------------------------------------------------------------------------
#define TILE_B 10240   // 128 rows x (64B data + 16B pad)
#define GSTR 40        // smem row stride in halves

template <bool SPLIT, bool BIAS, int NSTAGE>
__global__ __launch_bounds__(256, SPLIT ? 1 : 2)
void gemm_h2(const __half* __restrict__ Ah, const __half* __restrict__ Al,
             const __half* __restrict__ Bh, const __half* __restrict__ Bl,
             const float* __restrict__ bias0, const float* __restrict__ bias1,
             __half* __restrict__ Chi, __half* __restrict__ Clo,
             int M, int N, int K)
{
    extern __shared__ __align__(16) char sm[];
    const uint32_t sb = smem_u32(sm);
    const uint32_t PS = (SPLIT ? 4 : 2) * TILE_B;

    const int tid  = threadIdx.x;
    const int wid  = tid >> 5, lane = tid & 31;
    const int wm   = wid & 3,  wn   = wid >> 2;
    const int g    = lane >> 2, tig = lane & 3;
    const int row0 = blockIdx.y << 7;
    const int col0 = blockIdx.x << 7;

    const int ra    = tid >> 1;
    const int cbase = (tid & 1) << 4;
    const uint32_t dst_l = (uint32_t)ra * 80u + ((uint32_t)(tid & 1) << 5);

    const int t8 = lane >> 3, r8 = lane & 7;
    uint32_t aoff[2];
#pragma unroll
    for (int mi = 0; mi < 2; mi++) {
        int arow = wm * 32 + mi * 16 + (t8 & 1) * 8 + r8;
        aoff[mi] = (uint32_t)(arow * GSTR + (t8 >> 1) * 8) * 2u;
    }
    uint32_t boff[4];
#pragma unroll
    for (int j = 0; j < 4; j++) {
        int nrow = wn * 64 + (2 * j + (t8 >> 1)) * 8 + r8;
        boff[j] = (uint32_t)(nrow * GSTR + (t8 & 1) * 8) * 2u;
    }

    const int nt = K >> 5;

    float acc[2][8][4];
#pragma unroll
    for (int mi = 0; mi < 2; mi++)
#pragma unroll
        for (int ni = 0; ni < 8; ni++)
#pragma unroll
            for (int q = 0; q < 4; q++) acc[mi][ni][q] = 0.0f;

    auto issue = [&](int t, int stage) {
        const int koff = t << 5;
        const uint32_t base = sb + (uint32_t)stage * PS;
        const __half* ash = Ah + (size_t)(row0 + ra) * K + koff + cbase;
        cpa16(base + dst_l, ash);
        cpa16(base + dst_l + 16, ash + 8);
        const __half* bsh = Bh + (size_t)(col0 + ra) * K + koff + cbase;
        const uint32_t bbase = base + (SPLIT ? 2 : 1) * TILE_B;
        cpa16(bbase + dst_l, bsh);
        cpa16(bbase + dst_l + 16, bsh + 8);
        if (SPLIT) {
            const __half* asl = Al + (size_t)(row0 + ra) * K + koff + cbase;
            cpa16(base + TILE_B + dst_l, asl);
            cpa16(base + TILE_B + dst_l + 16, asl + 8);
            const __half* bsl = Bl + (size_t)(col0 + ra) * K + koff + cbase;
            cpa16(base + 3 * TILE_B + dst_l, bsl);
            cpa16(base + 3 * TILE_B + dst_l + 16, bsl + 8);
        }
        cpa_commit();
    };

#pragma unroll
    for (int s = 0; s < NSTAGE - 1; s++) issue(s, s);

    for (int t = 0; t < nt; t++) {
        cpa_wait<NSTAGE - 2>();
        __syncthreads();
        const int nxt = t + NSTAGE - 1;
        if (nxt < nt) issue(nxt, nxt % NSTAGE);

        const uint32_t base = sb + (uint32_t)(t % NSTAGE) * PS;
        const uint32_t sAh = base;
        const uint32_t sAl = base + TILE_B;
        const uint32_t sBh = base + (SPLIT ? 2 : 1) * TILE_B;
        const uint32_t sBl = base + 3 * TILE_B;

#pragma unroll
        for (int ks = 0; ks < 2; ks++) {
            uint32_t ah[2][4], al[2][4];
#pragma unroll
            for (int mi = 0; mi < 2; mi++) {
                ldsm4(ah[mi], sAh + aoff[mi] + ks * 32);
                if (SPLIT) ldsm4(al[mi], sAl + aoff[mi] + ks * 32);
            }
#pragma unroll
            for (int j = 0; j < 4; j++) {
                uint32_t qh[4], ql[4];
                ldsm4(qh, sBh + boff[j] + ks * 32);
                if (SPLIT) ldsm4(ql, sBl + boff[j] + ks * 32);
#pragma unroll
                for (int nb = 0; nb < 2; nb++) {
                    const int ni = 2 * j + nb;
#pragma unroll
                    for (int mi = 0; mi < 2; mi++) {
                        mma16816(acc[mi][ni], ah[mi], qh[2 * nb], qh[2 * nb + 1]);
                        if (SPLIT) {
                            mma16816(acc[mi][ni], ah[mi], ql[2 * nb], ql[2 * nb + 1]);
                            mma16816(acc[mi][ni], al[mi], qh[2 * nb], qh[2 * nb + 1]);
                        }
                    }
                }
            }
        }
    }

    // Epilogue: write fp16 hi/lo
#pragma unroll
    for (int mi = 0; mi < 2; mi++) {
#pragma unroll
        for (int ni = 0; ni < 8; ni++) {
            const int r = row0 + wm * 32 + mi * 16 + g;
            const int c = col0 + wn * 64 + ni * 8 + tig * 2;
            float b0 = 0.0f, b1 = 0.0f;
            if (BIAS) {
                const float* bp = (c < 256) ? bias0 + c : bias1 + (c - 256);
                b0 = bp[0]; b1 = bp[1];
            }
#pragma unroll
            for (int h = 0; h < 2; h++) {
                const int rr = r + h * 8;
                float x0 = acc[mi][ni][2 * h] + b0;
                float x1 = acc[mi][ni][2 * h + 1] + b1;
                __half h0 = __float2half_rn(x0), h1 = __float2half_rn(x1);
                __half l0 = __float2half_rn(x0 - __half2float(h0));
                __half l1 = __float2half_rn(x1 - __half2float(h1));
                *(__half2*)(Chi + (size_t)rr * N + c) = __halves2half2(h0, h1);
                *(__half2*)(Clo + (size_t)rr * N + c) = __halves2half2(l0, l1);
            }
        }
    }
}

// ---------------------------------------------------------------------------
// attn: sim = theta@phi^T/16 via split-fp16 MMA, mask, softmax -> R (fp32 +
// fp16 hi/lo). One block per batch. theta = TP cols 0-255, phi = cols 256-511.
// ---------------------------------------------------------------------------
#define AT_KP 136
#define AT_TH 0
#define AT_TL 17408
#define AT_PH 34816
#define AT_PL 52224
#define AT_SIM 69632
#define AT_CX 87040
#define AT_CY 87296
#define AT_SMEM 87552

__global__ __launch_bounds__(256, 2)
void attn_mma(const __half* __restrict__ TPh, const __half* __restrict__ TPl,
              const float* __restrict__ boxes, float* __restrict__ Rout,
              __half* __restrict__ Rhi, __half* __restrict__ Rlo)
{
    extern __shared__ __align__(16) char smc[];
    const uint32_t sb = smem_u32(smc);
    float* simb = (float*)(smc + AT_SIM);
    float* cx   = (float*)(smc + AT_CX);
    float* cy   = (float*)(smc + AT_CY);

    const int b   = blockIdx.x;
    const int tid = threadIdx.x;
    const int wid = tid >> 5, lane = tid & 31;
    const int wm  = wid & 3,  wn  = wid >> 2;
    const int g   = lane >> 2, tig = lane & 3;
    const int t8  = lane >> 3, r8  = lane & 7;

    if (tid < 64) {
        const float* bx = boxes + (size_t)b * 256 + tid * 4;
        cx[tid] = (bx[0] + bx[2]) * 0.5f;
        cy[tid] = (bx[1] + bx[3]) * 0.5f;
    }

    const uint32_t a_off =
        (uint32_t)((wm * 16 + (t8 & 1) * 8 + r8) * AT_KP + (t8 >> 1) * 8) * 2u;
    uint32_t b_off[2];
#pragma unroll
    for (int j = 0; j < 2; j++)
        b_off[j] = (uint32_t)((wn * 32 + (2 * j + (t8 >> 1)) * 8 + r8) * AT_KP +
                              (t8 & 1) * 8) * 2u;

    float acc[4][4];
#pragma unroll
    for (int ni = 0; ni < 4; ni++)
#pragma unroll
        for (int q = 0; q < 4; q++) acc[ni][q] = 0.0f;

    for (int kc = 0; kc < 2; kc++) {
#pragma unroll
        for (int i = 0; i < 4; i++) {
            const int u = tid + (i << 8);
            const int row = u >> 4, cu = u & 15;
            const size_t srow = ((size_t)b * 64 + row) * 512;
            const int colT = kc * 128 + cu * 8;
            const uint32_t dl = (uint32_t)(row * AT_KP + cu * 8) * 2u;
            cpa16(sb + AT_TH + dl, TPh + srow + colT);
            cpa16(sb + AT_TL + dl, TPl + srow + colT);
            cpa16(sb + AT_PH + dl, TPh + srow + 256 + colT);
            cpa16(sb + AT_PL + dl, TPl + srow + 256 + colT);
        }
        cpa_commit();
        cpa_wait<0>();
        __syncthreads();

#pragma unroll
        for (int ks = 0; ks < 8; ks++) {
            uint32_t ah[4], al[4];
            ldsm4(ah, sb + AT_TH + a_off + ks * 32);
            ldsm4(al, sb + AT_TL + a_off + ks * 32);
#pragma unroll
            for (int j = 0; j < 2; j++) {
                uint32_t qh[4], ql[4];
                ldsm4(qh, sb + AT_PH + b_off[j] + ks * 32);
                ldsm4(ql, sb + AT_PL + b_off[j] + ks * 32);
#pragma unroll
                for (int nb = 0; nb < 2; nb++) {
                    const int ni = 2 * j + nb;
                    mma16816(acc[ni], ah, qh[2 * nb], qh[2 * nb + 1]);
                    mma16816(acc[ni], ah, ql[2 * nb], ql[2 * nb + 1]);
                    mma16816(acc[ni], al, qh[2 * nb], qh[2 * nb + 1]);
                }
            }
        }
        __syncthreads();
    }

    // mask + store logits
    const float THR = 31.4f, NEG = __int_as_float(0xff800000);
#pragma unroll
    for (int ni = 0; ni < 4; ni++) {
        const int cm = wn * 32 + ni * 8 + tig * 2;
#pragma unroll
        for (int h = 0; h < 2; h++) {
            const int rn = wm * 16 + g + h * 8;
            const float cxr = cx[rn], cyr = cy[rn];
#pragma unroll
            for (int e = 0; e < 2; e++) {
                const int m = cm + e;
                float dx = cxr - cx[m], dy = cyr - cy[m];
                float d = sqrtf(dx * dx + dy * dy);
                simb[rn * 68 + m] = (d > THR) ? NEG : acc[ni][2 * h + e] * 0.0625f;
            }
        }
    }
    __syncthreads();

    // softmax: 4 threads per row
    {
        const int row = tid >> 2, q = tid & 3;
        float* sp = simb + row * 68 + q * 16;
        float v[16];
#pragma unroll
        for (int i = 0; i < 16; i += 4) {
            float4 t = *(float4*)(sp + i);
            v[i] = t.x; v[i + 1] = t.y; v[i + 2] = t.z; v[i + 3] = t.w;
        }
        float mx = v[0];
#pragma unroll
        for (int i = 1; i < 16; i++) mx = fmaxf(mx, v[i]);
        mx = fmaxf(mx, __shfl_xor_sync(0xffffffffu, mx, 1));
        mx = fmaxf(mx, __shfl_xor_sync(0xffffffffu, mx, 2));
        float s = 0.0f;
#pragma unroll
        for (int i = 0; i < 16; i++) { v[i] = __expf(v[i] - mx); s += v[i]; }
        s += __shfl_xor_sync(0xffffffffu, s, 1);
        s += __shfl_xor_sync(0xffffffffu, s, 2);
        const float inv = 1.0f / s;

        float* ro = Rout + (size_t)b * 4096 + row * 64 + q * 16;
        const size_t rbase = ((size_t)b * 64 + row) * 64 + q * 16;
#pragma unroll
        for (int i = 0; i < 16; i += 4) {
            float r0 = v[i] * inv, r1 = v[i + 1] * inv;
            float r2 = v[i + 2] * inv, r3 = v[i + 3] * inv;
            *(float4*)(ro + i) = make_float4(r0, r1, r2, r3);
            __half h0 = __float2half_rn(r0), h1 = __float2half_rn(r1);
            __half h2 = __float2half_rn(r2), h3 = __float2half_rn(r3);
            *(__half2*)(Rhi + rbase + i)     = __halves2half2(h0, h1);
            *(__half2*)(Rhi + rbase + i + 2) = __halves2half2(h2, h3);
            __half l0 = __float2half_rn(r0 - __half2float(h0));
            __half l1 = __float2half_rn(r1 - __half2float(h1));
            __half l2 = __float2half_rn(r2 - __half2float(h2));
            __half l3 = __float2half_rn(r3 - __half2float(h3));
            *(__half2*)(Rlo + rbase + i)     = __halves2half2(l0, l1);
            *(__half2*)(Rlo + rbase + i + 2) = __halves2half2(l2, l3);
        }
    }
}

// ---------------------------------------------------------------------------
// rg: out = relu(R @ G) via split-fp16 MMA. Block: batch b x 256-col chunk.
// R [64,64] (A, k-major), G [64,256] (B row-major -> ldmatrix.trans).
// ---------------------------------------------------------------------------
#define RG_RP 72
#define RG_GP 264
#define RG_RH 0
#define RG_RL 9216
#define RG_GH 18432
#define RG_GL 52224
#define RG_SMEM 86016

__global__ __launch_bounds__(256, 2)
void rg_mma(const __half* __restrict__ Rh, const __half* __restrict__ Rl,
            const __half* __restrict__ Gh, const __half* __restrict__ Gl,
            float* __restrict__ out)
{
    extern __shared__ __align__(16) char smc[];
    const uint32_t sb = smem_u32(smc);

    const int b   = blockIdx.y;
    const int cc  = blockIdx.x;         // 256-col chunk
    const int tid = threadIdx.x;
    const int wid = tid >> 5, lane = tid & 31;
    const int wm  = wid & 3,  wn  = wid >> 2;
    const int g   = lane >> 2, tig = lane & 3;
    const int t8  = lane >> 3, r8  = lane & 7;

    // loads: R tile 64x64 (512 chunk-pairs), G tile 64x256 (2048 chunk-pairs)
#pragma unroll
    for (int i = 0; i < 2; i++) {
        const int u = tid + (i << 8);
        const int row = u >> 3, cu = u & 7;
        const size_t srow = ((size_t)b * 64 + row) * 64 + cu * 8;
        const uint32_t dl = (uint32_t)(row * RG_RP + cu * 8) * 2u;
        cpa16(sb + RG_RH + dl, Rh + srow);
        cpa16(sb + RG_RL + dl, Rl + srow);
    }
#pragma unroll
    for (int i = 0; i < 8; i++) {       // FIX (was i < 4): cover all 64 G rows
        const int u = tid + (i << 8);
        const int row = u >> 5, cu = u & 31;
        const size_t srow = ((size_t)b * 64 + row) * 1024 + cc * 256 + cu * 8;
        const uint32_t dl = (uint32_t)(row * RG_GP + cu * 8) * 2u;
        cpa16(sb + RG_GH + dl, Gh + srow);
        cpa16(sb + RG_GL + dl, Gl + srow);
    }
    cpa_commit();
    cpa_wait<0>();
    __syncthreads();

    const uint32_t a_off =
        (uint32_t)((wm * 16 + (t8 & 1) * 8 + r8) * RG_RP + (t8 >> 1) * 8) * 2u;

    float acc[16][4];
#pragma unroll
    for (int ni = 0; ni < 16; ni++)
#pragma unroll
        for (int q = 0; q < 4; q++) acc[ni][q] = 0.0f;

#pragma unroll
    for (int ks = 0; ks < 4; ks++) {
        uint32_t ah[4], al[4];
        ldsm4(ah, sb + RG_RH + a_off + ks * 32);
        ldsm4(al, sb + RG_RL + a_off + ks * 32);
#pragma unroll
        for (int j = 0; j < 8; j++) {
            const uint32_t gl =
                (uint32_t)((ks * 16 + (lane & 15)) * RG_GP + wn * 128 + j * 16 +
                           (lane >> 4) * 8) * 2u;
            uint32_t qh[4], ql[4];
            ldsm4t(qh, sb + RG_GH + gl);
            ldsm4t(ql, sb + RG_GL + gl);
#pragma unroll
            for (int nb = 0; nb < 2; nb++) {
                const int ni = 2 * j + nb;
                mma16816(acc[ni], ah, qh[2 * nb], qh[2 * nb + 1]);
                mma16816(acc[ni], ah, ql[2 * nb], ql[2 * nb + 1]);
                mma16816(acc[ni], al, qh[2 * nb], qh[2 * nb + 1]);
            }
        }
    }

    float* ob = out + (size_t)b * 65536 + cc * 256;
#pragma unroll
    for (int ni = 0; ni < 16; ni++) {
        const int r = wm * 16 + g;
        const int c = wn * 128 + ni * 8 + tig * 2;
        *(float2*)(ob + (size_t)r * 1024 + c) =
            make_float2(fmaxf(acc[ni][0], 0.0f), fmaxf(acc[ni][1], 0.0f));
        *(float2*)(ob + (size_t)(r + 8) * 1024 + c) =
            make_float2(fmaxf(acc[ni][2], 0.0f), fmaxf(acc[ni][3], 0.0f));
    }
}

// ---------------------------------------------------------------------------
extern "C" void kernel_launch(void* const* d_in, const int* in_sizes, int n_in,
                              void* d_out, int out_size)
{
    const float* feats   = (const float*)d_in[0];
    const float* boxes   = (const float*)d_in[1];
    const float* W_theta = (const float*)d_in[2];
    const float* b_theta = (const float*)d_in[3];
    const float* W_phi   = (const float*)d_in[4];
    const float* b_phi   = (const float*)d_in[5];
    const float* W_gcn   = (const float*)d_in[6];

    float* out = (float*)d_out;
    float* R   = out + OUT_OFF;

    __half *Ahi, *Alo, *wch, *wcl, *wgh, *wgl, *tph, *tpl, *gh, *gl, *rh, *rl;
    cudaGetSymbolAddress((void**)&Ahi, g_Ahi);
    cudaGetSymbolAddress((void**)&Alo, g_Alo);
    cudaGetSymbolAddress((void**)&wch, g_Wc_hi);
    cudaGetSymbolAddress((void**)&wcl, g_Wc_lo);
    cudaGetSymbolAddress((void**)&wgh, g_Wg_hi);
    cudaGetSymbolAddress((void**)&wgl, g_Wg_lo);
    cudaGetSymbolAddress((void**)&tph, g_TPh);
    cudaGetSymbolAddress((void**)&tpl, g_TPl);
    cudaGetSymbolAddress((void**)&gh,  g_Gh);
    cudaGetSymbolAddress((void**)&gl,  g_Gl);
    cudaGetSymbolAddress((void**)&rh,  g_Rh);
    cudaGetSymbolAddress((void**)&rl,  g_Rl);

    // 1) operand conversion
    const int n4 = MROWS * NFG_ / 4;
    split_feats<<<n4 / 256, 256>>>(feats, Ahi, Alo, n4);
    split_wt<<<dim3(8, 32), dim3(32, 8)>>>(W_theta, wch, wcl, NFG_, NFR_);
    split_wt<<<dim3(8, 32), dim3(32, 8)>>>(W_phi, wch + 256 * NFG_,
                                           wcl + 256 * NFG_, NFG_, NFR_);
    split_wt<<<dim3(32, 32), dim3(32, 8)>>>(W_gcn, wgh, wgl, NFG_, NFG_);

    // 2) fused theta|phi projection, single-pass 3-segment split fp16
    const int tp_smem = 3 * 4 * TILE_B;      // 122880
    cudaFuncSetAttribute(gemm_h2<true, true, 3>,
                         cudaFuncAttributeMaxDynamicSharedMemorySize, tp_smem);
    gemm_h2<true, true, 3><<<dim3(4, 256), 256, tp_smem>>>(
        Ahi, Alo, wch, wcl, b_theta, b_phi, tph, tpl, MROWS, 512, NFG_);

    // 3) G = feats @ W_gcn (single fp16 term), output fp16 hi/lo
    const int g_smem = 4 * 2 * TILE_B;       // 81920
    cudaFuncSetAttribute(gemm_h2<false, false, 4>,
                         cudaFuncAttributeMaxDynamicSharedMemorySize, g_smem);
    gemm_h2<false, false, 4><<<dim3(8, 256), 256, g_smem>>>(
        Ahi, nullptr, wgh, nullptr, nullptr, nullptr, gh, gl, MROWS, NFG_, NFG_);

    // 4) attention + softmax -> relation_graph (+ fp16 hi/lo for rg)
    cudaFuncSetAttribute(attn_mma,
                         cudaFuncAttributeMaxDynamicSharedMemorySize, AT_SMEM);
    attn_mma<<<BB, 256, AT_SMEM>>>(tph, tpl, boxes, R, rh, rl);

    // 5) out = relu(R @ G)
    cudaFuncSetAttribute(rg_mma,
                         cudaFuncAttributeMaxDynamicSharedMemorySize, RG_SMEM);
    rg_mma<<<dim3(4, BB), 256, RG_SMEM>>>(rh, rl, gh, gl, out);
}